// round 10
// baseline (speedup 1.0000x reference)
#include <cuda_runtime.h>
#include <cstdint>

#define D_DIM 128

// ---------------- device scratch: single struct -> one memset ----------------
struct alignas(16) Scratch {
    float  M[D_DIM * D_DIM];            // M = U U^T            (offset 0)
    float  W[D_DIM * D_DIM];            // W = U diag(cnt) U^T  (offset 64KB)
    float  cnt[4096];                   // histogram of G
    double acc;                         // dots accumulator
    double tr;                          // trace(M .* W)
    unsigned histdone;                  // blocks 0..31 past hist phase
    unsigned mwdone;                    // blocks 0..31 past MW phase
    unsigned done;                      // all blocks finished
};
__device__ Scratch g_s;

__device__ __forceinline__ long long ld_idx(const void* p, long long i, int is64) {
    if (is64) return ((const long long*)p)[i];
    return (long long)((const int*)p)[i];
}

// ---------------- THE one big kernel (plus a memset node) ----------------
__global__ void __launch_bounds__(256, 8)
k_fused(const float* __restrict__ Ub, const float* __restrict__ U,
        const void* midx, const void* segs, const void* Gp,
        long long N, int P, int PK, double inv_den, float* out) {
    const int tid = threadIdx.x;
    const int bid = blockIdx.x;
    const int nb  = gridDim.x;

    // ---- dtype probe (warp 0): int32 reinterpreted as int64 -> high-word junk
    __shared__ int s_is64;
    if (tid < 32) {
        const long long* p64 = (const long long*)midx;
        int m = (int)(N < 32 ? N : 32);
        int bad = 0;
        if (tid < m) {
            long long v = p64[tid];
            bad = (v < 0 || v >= N) ? 1 : 0;
        }
        unsigned b = __ballot_sync(0xFFFFFFFFu, bad);
        if (tid == 0) s_is64 = (b == 0) ? 1 : 0;
    }
    __syncthreads();
    const int is64 = s_is64;

    __shared__ double red[8];
    __shared__ int s_flag;

    // ============ side work: blocks 0..31 (co-resident in wave 1) ============
    if (bid < 32) {
        // ---- hist: 32k global atomics into cnt
        for (int i = bid * 256 + tid; i < PK; i += 32 * 256) {
            int g = (int)ld_idx(Gp, i, is64);
            atomicAdd(&g_s.cnt[g], 1.0f);
        }
        __threadfence();
        __syncthreads();
        if (tid == 0) {
            atomicAdd(&g_s.histdone, 1u);
            while (*(volatile unsigned*)&g_s.histdone < 32u)
                __nanosleep(32);
        }
        __syncthreads();
        __threadfence();

        // ---- MW: block owns rows [bid*4, bid*4+4) of M and W. Plain stores.
        // thread t: column j = t&127, row pair ia/ib = bid*4 + (t>>7)*2 + {0,1}
        __shared__ float sh[16][D_DIM];   // 16 U-columns (each a 128-vector)
        __shared__ float shc[16];
        const int jcol = tid & 127;
        const int ia = bid * 4 + (tid >> 7) * 2;
        const int ib = ia + 1;
        float m0 = 0.f, m1 = 0.f, w0 = 0.f, w1 = 0.f;
        const int nchunk = (P + 15) / 16;

        for (int c = 0; c < nchunk; c++) {
            int p0 = c * 16;
            __syncthreads();
            for (int e = tid; e < 16 * D_DIM; e += 256) {
                int d = e >> 4, pc = e & 15;
                int p = p0 + pc;
                sh[pc][d] = (p < P) ? U[(size_t)d * P + p] : 0.f;
            }
            if (tid < 16) {
                int p = p0 + tid;
                shc[tid] = (p < P) ? g_s.cnt[p] : 0.f;
            }
            __syncthreads();
#pragma unroll
            for (int pc = 0; pc < 16; pc++) {
                float b  = sh[pc][jcol];
                float cw = shc[pc];
                float a0 = sh[pc][ia];
                float a1 = sh[pc][ib];
                m0 += a0 * b;
                m1 += a1 * b;
                w0 += (cw * a0) * b;
                w1 += (cw * a1) * b;
            }
        }
        g_s.M[ia * D_DIM + jcol] = m0;
        g_s.M[ib * D_DIM + jcol] = m1;
        g_s.W[ia * D_DIM + jcol] = w0;
        g_s.W[ib * D_DIM + jcol] = w1;
        __threadfence();
        if (tid == 0) {
            unsigned t = atomicAdd(&g_s.mwdone, 1u);
            s_flag = (t == 31u) ? 1 : 0;
        }
        __syncthreads();

        // ---- last MW block: trace(M .* W) -> g_s.tr
        if (s_flag) {
            __threadfence();
            double tr = 0.0;
            int base = tid * 64;              // 256 threads x 64 elements
#pragma unroll
            for (int q = 0; q < 16; q++) {
                float4 mv = *(const float4*)(g_s.M + base + q * 4);
                float4 wv = *(const float4*)(g_s.W + base + q * 4);
                tr += (double)mv.x * wv.x + (double)mv.y * wv.y
                    + (double)mv.z * wv.z + (double)mv.w * wv.w;
            }
            unsigned mask = 0xFFFFFFFFu;
#pragma unroll
            for (int off = 16; off > 0; off >>= 1)
                tr += __shfl_down_sync(mask, tr, off);
            int lane = tid & 31, warp = tid >> 5;
            if (lane == 0) red[warp] = tr;
            __syncthreads();
            if (warp == 0) {
                double t = (lane < 8) ? red[lane] : 0.0;
#pragma unroll
                for (int off = 4; off > 0; off >>= 1)
                    t += __shfl_down_sync(mask, t, off);
                if (lane == 0) g_s.tr = t;
            }
            __threadfence();   // tr visible before this block's done++
        }
    }

    // ============ main dots pass: EXACT R1 body, all blocks ============
    long long j = (long long)bid * 256 + tid;
    double val = 0.0;
    if (j < N) {
        long long mi = ld_idx(midx, j, is64);
        int g = (int)ld_idx(segs, j, is64);
        const float* ub = Ub + mi;
        const float* uu = U + g;
        float acc = 0.f;
#pragma unroll 8
        for (int d = 0; d < D_DIM; d++)
            acc += __ldg(ub + (size_t)d * N) * __ldg(uu + (size_t)d * P);
        val = (double)acc * (double)acc;
    }

    // ---- block reduce (double), publish, last block finalizes
    __syncthreads();                 // red[] reuse safety (MW trace path)
    if (tid == 0) s_flag = 0;
    __syncthreads();
    unsigned mask = 0xFFFFFFFFu;
#pragma unroll
    for (int off = 16; off > 0; off >>= 1)
        val += __shfl_down_sync(mask, val, off);
    int lane = tid & 31, warp = tid >> 5;
    if (lane == 0) red[warp] = val;
    __syncthreads();
    if (warp == 0) {
        double s = (lane < 8) ? red[lane] : 0.0;
#pragma unroll
        for (int off = 4; off > 0; off >>= 1)
            s += __shfl_down_sync(mask, s, off);
        if (lane == 0) {
            atomicAdd(&g_s.acc, s);
            __threadfence();
            unsigned t = atomicAdd(&g_s.done, 1u);
            if (t == (unsigned)nb - 1u) s_flag = 1;
        }
    }
    __syncthreads();

    // last-done block: tr was published before the trace-block's done++ (which
    // precedes ours in the done order), so it is visible here after the fence.
    if (s_flag && tid == 0) {
        __threadfence();
        double dots_total = *(volatile double*)&g_s.acc;
        double tr = *(volatile double*)&g_s.tr;
        out[0] = (float)(-0.5 * dots_total - 0.5 * tr * inv_den);
    }
}

// ---------------- launch ----------------
extern "C" void kernel_launch(void* const* d_in, const int* in_sizes, int n_in,
                              void* d_out, int out_size) {
    const float* U_base = (const float*)d_in[0];
    const float* U      = (const float*)d_in[1];
    const void*  midx   = d_in[2];
    const void*  segs   = d_in[3];
    const void*  Gp     = d_in[4];

    long long N = in_sizes[2];
    int D = (int)((long long)in_sizes[0] / N); // = 128
    int P = in_sizes[1] / D;                   // = 1024
    int PK = in_sizes[4];                      // P*K
    int K = PK / P;
    (void)D; (void)n_in;

    float* out = (float*)d_out;
    (void)out_size;

    // Zero ALL scratch with one memset node (graph-capturable).
    void* pS;
    cudaGetSymbolAddress(&pS, g_s);
    cudaMemsetAsync(pS, 0, sizeof(Scratch));

    long long nblk = (N + 255) / 256;
    if (nblk < 32) nblk = 32;                  // side-work needs 32 blocks
    double inv_den = 1.0 / ((double)P * (double)K * (double)P);
    k_fused<<<(unsigned)nblk, 256>>>(U_base, U, midx, segs, Gp,
                                     N, P, PK, inv_den, out);
}

// round 13
// speedup vs baseline: 1.0971x; 1.0971x over previous
#include <cuda_runtime.h>
#include <cstdint>

#define D_DIM 128

// ---------------- device scratch: single struct -> one memset ----------------
struct alignas(16) Scratch {
    float  M[D_DIM * D_DIM];            // M = U U^T            (offset 0)
    float  W[D_DIM * D_DIM];            // W = U diag(cnt) U^T  (offset 64KB)
    double acc;                         // dots accumulator
    double tr;                          // trace(M .* W)
    unsigned mwdone;                    // blocks 0..31 past MW phase
    unsigned done;                      // all blocks finished
};
__device__ Scratch g_s;

__device__ __forceinline__ long long ld_idx(const void* p, long long i, int is64) {
    if (is64) return ((const long long*)p)[i];
    return (long long)((const int*)p)[i];
}

// ---------------- THE one big kernel (plus a memset node) ----------------
// NO inter-block spin-waits anywhere: every sync is a forward-progress-only
// atomic counter ("last one does the work"), so the kernel cannot hang.
__global__ void __launch_bounds__(256, 8)
k_fused(const float* __restrict__ Ub, const float* __restrict__ U,
        const void* midx, const void* segs, const void* Gp,
        long long N, int P, int PK, double inv_den, float* out) {
    const int tid = threadIdx.x;
    const int bid = blockIdx.x;
    const int nb  = gridDim.x;

    // ---- dtype probe (warp 0): int32 reinterpreted as int64 -> high-word junk
    __shared__ int s_is64;
    if (tid < 32) {
        const long long* p64 = (const long long*)midx;
        int m = (int)(N < 32 ? N : 32);
        int bad = 0;
        if (tid < m) {
            long long v = p64[tid];
            bad = (v < 0 || v >= N) ? 1 : 0;
        }
        unsigned b = __ballot_sync(0xFFFFFFFFu, bad);
        if (tid == 0) s_is64 = (b == 0) ? 1 : 0;
    }
    __syncthreads();
    const int is64 = s_is64;

    __shared__ double red[8];
    __shared__ int s_flag;

    // ============ side work: blocks 0..31 ============
    // Each side block builds its OWN shared histogram of G (no cross-block
    // dependency), then computes its MW share (8 of 64 chunks, one 64x64
    // quadrant, register tiles, atomicAdd merge).  Requires P <= 4096.
    if (bid < 32 && P <= 4096) {
        __shared__ unsigned shist[4096];
        for (int p = tid; p < P; p += 256) shist[p] = 0u;
        __syncthreads();
        for (int i = tid; i < PK; i += 256) {
            int g = (int)ld_idx(Gp, i, is64);
            atomicAdd(&shist[g], 1u);
        }
        __syncthreads();

        // ---- MW: M = U U^T, W = U diag(cnt) U^T
        __shared__ float sh[16][D_DIM];
        __shared__ float shc[16];
        int grp  = bid >> 2;          // 0..7 -> chunk set {grp, grp+8, ...}
        int quad = bid & 3;           // 64x64 quadrant
        int ti = tid & 15, tj = tid >> 4;
        int i0 = (quad & 1) * 64 + ti * 4;
        int j0 = (quad >> 1) * 64 + tj * 4;
        int nchunk = (P + 15) / 16;

        float m[4][4] = {{0}}, w[4][4] = {{0}};
        for (int c = grp; c < nchunk; c += 8) {
            int p0 = c * 16;
            __syncthreads();
            for (int e = tid; e < 16 * D_DIM; e += 256) {
                int d = e >> 4, pc = e & 15;
                int p = p0 + pc;
                sh[pc][d] = (p < P) ? U[(size_t)d * P + p] : 0.f;
            }
            if (tid < 16) {
                int p = p0 + tid;
                shc[tid] = (p < P) ? (float)shist[p] : 0.f;
            }
            __syncthreads();
#pragma unroll
            for (int pc = 0; pc < 16; pc++) {
                float cw = shc[pc];
                float a[4], ca[4], b[4];
#pragma unroll
                for (int x = 0; x < 4; x++) { a[x] = sh[pc][i0 + x]; ca[x] = cw * a[x]; }
#pragma unroll
                for (int y = 0; y < 4; y++) b[y] = sh[pc][j0 + y];
#pragma unroll
                for (int x = 0; x < 4; x++)
#pragma unroll
                    for (int y = 0; y < 4; y++) {
                        m[x][y] += a[x] * b[y];
                        w[x][y] += ca[x] * b[y];
                    }
            }
        }
#pragma unroll
        for (int x = 0; x < 4; x++)
#pragma unroll
            for (int y = 0; y < 4; y++) {
                int idx = (i0 + x) * D_DIM + (j0 + y);
                atomicAdd(&g_s.M[idx], m[x][y]);
                atomicAdd(&g_s.W[idx], w[x][y]);
            }
        __threadfence();
        if (tid == 0) {
            unsigned t = atomicAdd(&g_s.mwdone, 1u);
            s_flag = (t == 31u) ? 1 : 0;
        }
        __syncthreads();

        // ---- last MW block: trace(M .* W) -> g_s.tr
        if (s_flag) {
            __threadfence();
            double tr = 0.0;
            int base = tid * 64;              // 256 threads x 64 elements
#pragma unroll
            for (int q = 0; q < 16; q++) {
                float4 mv = *(const float4*)(g_s.M + base + q * 4);
                float4 wv = *(const float4*)(g_s.W + base + q * 4);
                tr += (double)mv.x * wv.x + (double)mv.y * wv.y
                    + (double)mv.z * wv.z + (double)mv.w * wv.w;
            }
            unsigned mask = 0xFFFFFFFFu;
#pragma unroll
            for (int off = 16; off > 0; off >>= 1)
                tr += __shfl_down_sync(mask, tr, off);
            int lane = tid & 31, warp = tid >> 5;
            if (lane == 0) red[warp] = tr;
            __syncthreads();
            if (warp == 0) {
                double t = (lane < 8) ? red[lane] : 0.0;
#pragma unroll
                for (int off = 4; off > 0; off >>= 1)
                    t += __shfl_down_sync(mask, t, off);
                if (lane == 0) g_s.tr = t;
            }
            __threadfence();   // tr visible before this block's done++
        }
    }

    // ============ main dots pass: EXACT R1/R9 body, all blocks ============
    long long j = (long long)bid * 256 + tid;
    double val = 0.0;
    if (j < N) {
        long long mi = ld_idx(midx, j, is64);
        int g = (int)ld_idx(segs, j, is64);
        const float* ub = Ub + mi;
        const float* uu = U + g;
        float acc = 0.f;
#pragma unroll 8
        for (int d = 0; d < D_DIM; d++)
            acc += __ldg(ub + (size_t)d * N) * __ldg(uu + (size_t)d * P);
        val = (double)acc * (double)acc;
    }

    // ---- block reduce (double), publish, last block finalizes
    __syncthreads();                 // red[]/s_flag reuse safety
    if (tid == 0) s_flag = 0;
    __syncthreads();
    unsigned mask = 0xFFFFFFFFu;
#pragma unroll
    for (int off = 16; off > 0; off >>= 1)
        val += __shfl_down_sync(mask, val, off);
    int lane = tid & 31, warp = tid >> 5;
    if (lane == 0) red[warp] = val;
    __syncthreads();
    if (warp == 0) {
        double s = (lane < 8) ? red[lane] : 0.0;
#pragma unroll
        for (int off = 4; off > 0; off >>= 1)
            s += __shfl_down_sync(mask, s, off);
        if (lane == 0) {
            atomicAdd(&g_s.acc, s);
            __threadfence();
            unsigned t = atomicAdd(&g_s.done, 1u);
            if (t == (unsigned)nb - 1u) s_flag = 1;
        }
    }
    __syncthreads();

    // last-done block: every side block's tr/MW publication (fenced) precedes
    // its own done++, all of which precede ours -> visible here.
    if (s_flag && tid == 0) {
        __threadfence();
        double dots_total = *(volatile double*)&g_s.acc;
        double tr = *(volatile double*)&g_s.tr;
        out[0] = (float)(-0.5 * dots_total - 0.5 * tr * inv_den);
    }
}

// ---------------- launch ----------------
extern "C" void kernel_launch(void* const* d_in, const int* in_sizes, int n_in,
                              void* d_out, int out_size) {
    const float* U_base = (const float*)d_in[0];
    const float* U      = (const float*)d_in[1];
    const void*  midx   = d_in[2];
    const void*  segs   = d_in[3];
    const void*  Gp     = d_in[4];

    long long N = in_sizes[2];
    int D = (int)((long long)in_sizes[0] / N); // = 128
    int P = in_sizes[1] / D;                   // = 1024
    int PK = in_sizes[4];                      // P*K
    int K = PK / P;
    (void)D; (void)n_in;

    float* out = (float*)d_out;
    (void)out_size;

    // Zero ALL scratch with one memset node (graph-capturable).
    void* pS;
    cudaGetSymbolAddress(&pS, g_s);
    cudaMemsetAsync(pS, 0, sizeof(Scratch));

    long long nblk = (N + 255) / 256;
    if (nblk < 32) nblk = 32;                  // side-work needs 32 blocks
    double inv_den = 1.0 / ((double)P * (double)K * (double)P);
    k_fused<<<(unsigned)nblk, 256>>>(U_base, U, midx, segs, Gp,
                                     N, P, PK, inv_den, out);
}

// round 14
// speedup vs baseline: 2.2231x; 2.0263x over previous
#include <cuda_runtime.h>
#include <cstdint>

#define D_DIM 128

// ---------------- device scratch: single struct -> one memset ----------------
struct alignas(16) Scratch {
    float  M[D_DIM * D_DIM];            // M = U U^T            (offset 0)
    float  W[D_DIM * D_DIM];            // W = U diag(cnt) U^T  (offset 64KB)
    float  cnt[4096];                   // histogram of G
    double acc;                         // dots accumulator
    double tr;                          // trace(M .* W)
    unsigned mwdone;                    // k_mw blocks finished
    unsigned done;                      // k_dots blocks finished
};
__device__ Scratch g_s;

__device__ __forceinline__ long long ld_idx(const void* p, long long i, int is64) {
    if (is64) return ((const long long*)p)[i];
    return (long long)((const int*)p)[i];
}

// Block-level dtype probe: warp 0 reads first <=32 int64 entries of merge_idx.
// int32 data reinterpreted as int64 has nonzero high words -> out of [0,N).
__device__ __forceinline__ int probe_is64(const void* merge_idx, long long N) {
    __shared__ int s_is64;
    if (threadIdx.x < 32) {
        const long long* p64 = (const long long*)merge_idx;
        int m = (int)(N < 32 ? N : 32);
        int bad = 0;
        if ((int)threadIdx.x < m) {
            long long v = p64[threadIdx.x];
            bad = (v < 0 || v >= N) ? 1 : 0;
        }
        unsigned b = __ballot_sync(0xFFFFFFFFu, bad);
        if (threadIdx.x == 0) s_is64 = (b == 0) ? 1 : 0;
    }
    __syncthreads();
    return s_is64;
}

// ---------------- kernel H: histogram of G (R6-proven) ----------------
__global__ void k_hist(const void* Gp, int total, const void* midx, long long N) {
    int is64 = probe_is64(midx, N);
    int i = blockIdx.x * blockDim.x + threadIdx.x;
    if (i < total) {
        int g = (int)ld_idx(Gp, i, is64);
        atomicAdd(&g_s.cnt[g], 1.0f);
    }
}

// ---------------- kernel MW: M/W build + last-block trace ----------------
// 32 blocks: grp=bid>>2 handles chunks {grp, grp+8, ...}, quad=bid&3 is the
// 64x64 output quadrant. Register 4x4 tiles, one atomic set at end (R6-proven).
// Last block to finish computes trace(M .* W) -> g_s.tr.
__global__ void __launch_bounds__(256)
k_mw(const float* __restrict__ U, int P) {
    __shared__ float sh[16][D_DIM];
    __shared__ float shc[16];
    const int tid = threadIdx.x;
    const int bid = blockIdx.x;

    int grp  = bid >> 2;
    int quad = bid & 3;
    int ti = tid & 15, tj = tid >> 4;
    int i0 = (quad & 1) * 64 + ti * 4;
    int j0 = (quad >> 1) * 64 + tj * 4;
    int nchunk = (P + 15) / 16;

    float m[4][4] = {{0}}, w[4][4] = {{0}};
    for (int c = grp; c < nchunk; c += 8) {
        int p0 = c * 16;
        __syncthreads();
        for (int e = tid; e < 16 * D_DIM; e += 256) {
            int d = e >> 4, pc = e & 15;
            int p = p0 + pc;
            sh[pc][d] = (p < P) ? U[(size_t)d * P + p] : 0.f;
        }
        if (tid < 16) {
            int p = p0 + tid;
            shc[tid] = (p < P) ? g_s.cnt[p] : 0.f;
        }
        __syncthreads();
#pragma unroll
        for (int pc = 0; pc < 16; pc++) {
            float cw = shc[pc];
            float a[4], ca[4], b[4];
#pragma unroll
            for (int x = 0; x < 4; x++) { a[x] = sh[pc][i0 + x]; ca[x] = cw * a[x]; }
#pragma unroll
            for (int y = 0; y < 4; y++) b[y] = sh[pc][j0 + y];
#pragma unroll
            for (int x = 0; x < 4; x++)
#pragma unroll
                for (int y = 0; y < 4; y++) {
                    m[x][y] += a[x] * b[y];
                    w[x][y] += ca[x] * b[y];
                }
        }
    }
#pragma unroll
    for (int x = 0; x < 4; x++)
#pragma unroll
        for (int y = 0; y < 4; y++) {
            int idx = (i0 + x) * D_DIM + (j0 + y);
            atomicAdd(&g_s.M[idx], m[x][y]);
            atomicAdd(&g_s.W[idx], w[x][y]);
        }

    // last block: trace(M .* W) -> g_s.tr
    __shared__ int s_last;
    __threadfence();
    if (tid == 0) {
        unsigned t = atomicAdd(&g_s.mwdone, 1u);
        s_last = (t == 31u) ? 1 : 0;
    }
    __syncthreads();
    if (s_last) {
        __threadfence();
        double tr = 0.0;
        int base = tid * 64;                  // 256 threads x 64 elements
#pragma unroll
        for (int q = 0; q < 16; q++) {
            float4 mv = *(const float4*)(g_s.M + base + q * 4);
            float4 wv = *(const float4*)(g_s.W + base + q * 4);
            tr += (double)mv.x * wv.x + (double)mv.y * wv.y
                + (double)mv.z * wv.z + (double)mv.w * wv.w;
        }
        __shared__ double red[8];
        unsigned mask = 0xFFFFFFFFu;
#pragma unroll
        for (int off = 16; off > 0; off >>= 1)
            tr += __shfl_down_sync(mask, tr, off);
        int lane = tid & 31, warp = tid >> 5;
        if (lane == 0) red[warp] = tr;
        __syncthreads();
        if (warp == 0) {
            double t = (lane < 8) ? red[lane] : 0.0;
#pragma unroll
            for (int off = 4; off > 0; off >>= 1)
                t += __shfl_down_sync(mask, t, off);
            if (lane == 0) g_s.tr = t;
        }
    }
}

// ---------------- kernel D: R1-exact dots + last-block finalize ----------
// tr is already in g_s.tr (k_mw precedes in stream order) -> finalize is free.
__global__ void __launch_bounds__(256)
k_dots(const float* __restrict__ Ub, const float* __restrict__ U,
       const void* midx, const void* segs,
       long long N, int P, double inv_den, float* out, int nb) {
    int is64 = probe_is64(midx, N);
    long long j = (long long)blockIdx.x * blockDim.x + threadIdx.x;

    double val = 0.0;
    if (j < N) {
        long long mi = ld_idx(midx, j, is64);
        int g = (int)ld_idx(segs, j, is64);
        const float* ub = Ub + mi;
        const float* uu = U + g;
        float acc = 0.f;
#pragma unroll 8
        for (int d = 0; d < D_DIM; d++)
            acc += __ldg(ub + (size_t)d * N) * __ldg(uu + (size_t)d * P);
        val = (double)acc * (double)acc;
    }

    // block reduce (256 threads) in double
    __shared__ double red[8];
    __shared__ int s_last;
    if (threadIdx.x == 0) s_last = 0;
    unsigned mask = 0xFFFFFFFFu;
#pragma unroll
    for (int off = 16; off > 0; off >>= 1)
        val += __shfl_down_sync(mask, val, off);
    int lane = threadIdx.x & 31, warp = threadIdx.x >> 5;
    if (lane == 0) red[warp] = val;
    __syncthreads();
    if (warp == 0) {
        double s = (lane < 8) ? red[lane] : 0.0;
#pragma unroll
        for (int off = 4; off > 0; off >>= 1)
            s += __shfl_down_sync(mask, s, off);
        if (lane == 0) {
            atomicAdd(&g_s.acc, s);
            __threadfence();
            unsigned t = atomicAdd(&g_s.done, 1u);
            if (t == (unsigned)nb - 1u) s_last = 1;
        }
    }
    __syncthreads();

    if (s_last && threadIdx.x == 0) {
        __threadfence();
        double dots_total = *(volatile double*)&g_s.acc;
        double tr = *(volatile double*)&g_s.tr;   // written before this kernel
        out[0] = (float)(-0.5 * dots_total - 0.5 * tr * inv_den);
    }
}

// ---------------- launch ----------------
extern "C" void kernel_launch(void* const* d_in, const int* in_sizes, int n_in,
                              void* d_out, int out_size) {
    const float* U_base = (const float*)d_in[0];
    const float* U      = (const float*)d_in[1];
    const void*  midx   = d_in[2];
    const void*  segs   = d_in[3];
    const void*  Gp     = d_in[4];

    long long N = in_sizes[2];
    int D = (int)((long long)in_sizes[0] / N); // = 128
    int P = in_sizes[1] / D;                   // = 1024
    int PK = in_sizes[4];                      // P*K
    int K = PK / P;
    (void)D; (void)n_in;

    float* out = (float*)d_out;
    (void)out_size;

    // Zero ALL scratch with one memset node (graph-capturable).
    void* pS;
    cudaGetSymbolAddress(&pS, g_s);
    cudaMemsetAsync(pS, 0, sizeof(Scratch));

    // H: histogram of G (128 blocks — R6-proven fast)
    k_hist<<<(PK + 255) / 256, 256>>>(Gp, PK, midx, N);

    // MW: build M/W + trace in last block (32 blocks — R6-proven fast)
    k_mw<<<32, 256>>>(U, P);

    // D: main HBM-bound pass (R1-exact) + inline finalize
    long long nblk = (N + 255) / 256;
    double inv_den = 1.0 / ((double)P * (double)K * (double)P);
    k_dots<<<(unsigned)nblk, 256>>>(U_base, U, midx, segs, N, P, inv_den, out, (int)nblk);
}